// round 14
// baseline (speedup 1.0000x reference)
#include <cuda_runtime.h>
#include <cuda_fp16.h>
#include <cstdint>
#include <cstddef>

#define NPTS   4096
#define MANCH  128
#define GC0    64
#define GC1    128
#define KNN    32
#define RR2    0.0225f
#define GTOT   64
#define FPS_THREADS 1024
#define FS     66    // B-fragment stride in words (64 + 2 pad)
#define FPS_SPLIT 64 // fps1 produces anchors [0,FPS_SPLIT), fps2 the rest

// Layer-1 weights (1KB — const-cache resident, warp-uniform reads)
__constant__ float4 cWd[GC0];
// Layer-2 weights as fp16x2 in m16n8k16 A-fragment layout (16KB, L1-resident)
__device__ uint32_t gWmF16[8 * 4 * 128];
// Ball-query output: [g][m][dt][c(3)][k(32)] fp32 displacements (9.4MB)
__device__ float gDisp[(size_t)GTOT * MANCH * 3 * 96];
// fps min-distance state carried across the split (1MB)
__device__ float gFpsDist[(size_t)GTOT * NPTS];

// Exact (non-FMA-contracted) squared distance: discrete decisions
// (radius threshold) match the JAX reference bit-for-bit.
__device__ __forceinline__ float dist2_precise(float ax, float ay, float az,
                                               float bx, float by, float bz) {
    float dx = __fsub_rn(ax, bx);
    float dy = __fsub_rn(ay, by);
    float dz = __fsub_rn(az, bz);
    return __fadd_rn(__fadd_rn(__fmul_rn(dx, dx), __fmul_rn(dy, dy)),
                     __fmul_rn(dz, dz));
}

// ---- packed f32x2 helpers (per-lane rounding identical to scalar ops) ----
typedef unsigned long long u64t;
__device__ __forceinline__ u64t pk2f(float lo, float hi) {
    u64t r; asm("mov.b64 %0, {%1, %2};" : "=l"(r) : "f"(lo), "f"(hi)); return r;
}
__device__ __forceinline__ void upk2f(float& lo, float& hi, u64t v) {
    asm("mov.b64 {%0, %1}, %2;" : "=f"(lo), "=f"(hi) : "l"(v));
}
__device__ __forceinline__ u64t sub2(u64t a, u64t b) {
    u64t d; asm("sub.rn.f32x2 %0, %1, %2;" : "=l"(d) : "l"(a), "l"(b)); return d;
}
__device__ __forceinline__ u64t mul2(u64t a, u64t b) {
    u64t d; asm("mul.rn.f32x2 %0, %1, %2;" : "=l"(d) : "l"(a), "l"(b)); return d;
}
__device__ __forceinline__ u64t add2(u64t a, u64t b) {
    u64t d; asm("add.rn.f32x2 %0, %1, %2;" : "=l"(d) : "l"(a), "l"(b)); return d;
}

__device__ __forceinline__ unsigned redux_max_u32(unsigned v) {
    unsigned r;
    asm("redux.sync.max.u32 %0, %1, 0xffffffff;" : "=r"(r) : "r"(v));
    return r;
}
__device__ __forceinline__ unsigned redux_min_u32(unsigned v) {
    unsigned r;
    asm("redux.sync.min.u32 %0, %1, 0xffffffff;" : "=r"(r) : "r"(v));
    return r;
}

// pack two fp32 -> fp16x2 (lo in low half)
__device__ __forceinline__ uint32_t pkh2(float lo, float hi) {
    uint32_t r;
    asm("cvt.rn.f16x2.f32 %0, %1, %2;" : "=r"(r) : "f"(hi), "f"(lo));
    return r;
}

__device__ __forceinline__ void mma_f16(float& d0, float& d1, float& d2, float& d3,
                                        uint32_t a0, uint32_t a1, uint32_t a2, uint32_t a3,
                                        uint32_t b0, uint32_t b1) {
    asm volatile(
        "mma.sync.aligned.m16n8k16.row.col.f32.f16.f16.f32 "
        "{%0,%1,%2,%3}, {%4,%5,%6,%7}, {%8,%9}, {%0,%1,%2,%3};"
        : "+f"(d0), "+f"(d1), "+f"(d2), "+f"(d3)
        : "r"(a0), "r"(a1), "r"(a2), "r"(a3), "r"(b0), "r"(b1));
}

// ---- shared fps machinery -------------------------------------------------
// One fps step: packed exact distance update + exact first-occurrence argmax.
// Returns new pivot via (px,py,pz). Template-free plain device function.
struct FpsState {
    u64t X2[2], Y2[2], Z2[2];
    float dist[4];
};

__device__ __forceinline__ void fps_steps(
    FpsState& st, float* sx, float* sy, float* sz,
    float redV[2][32], int redI[2][32],
    float& px, float& py, float& pz,
    int stepBeg, int stepEnd, int g, int tid, int lane, int wid,
    float* __restrict__ out) {
    for (int step = stepBeg; step < stepEnd; step++) {
        int par = step & 1;
        u64t pxx = pk2f(px, px), pyy = pk2f(py, py), pzz = pk2f(pz, pz);
        float nd[4];
#pragma unroll
        for (int p = 0; p < 2; p++) {
            u64t dx = sub2(st.X2[p], pxx);
            u64t dy = sub2(st.Y2[p], pyy);
            u64t dz = sub2(st.Z2[p], pzz);
            u64t d2 = add2(add2(mul2(dx, dx), mul2(dy, dy)), mul2(dz, dz));
            upk2f(nd[2 * p], nd[2 * p + 1], d2);
        }
        float bv = -1.0f;
#pragma unroll
        for (int s = 0; s < 4; s++) {
            st.dist[s] = fminf(st.dist[s], nd[s]);
            bv = fmaxf(bv, st.dist[s]);
        }
        unsigned wm = redux_max_u32(__float_as_uint(bv));
        unsigned ci = 0x7FFFFFFFu;
        if (__float_as_uint(st.dist[3]) == wm) ci = (unsigned)(tid + 3 * FPS_THREADS);
        if (__float_as_uint(st.dist[2]) == wm) ci = (unsigned)(tid + 2 * FPS_THREADS);
        if (__float_as_uint(st.dist[1]) == wm) ci = (unsigned)(tid + FPS_THREADS);
        if (__float_as_uint(st.dist[0]) == wm) ci = (unsigned)tid;
        unsigned wi = redux_min_u32(ci);
        if (lane == 0) { redV[par][wid] = __uint_as_float(wm); redI[par][wid] = (int)wi; }
        __syncthreads();
        float    v  = redV[par][lane];
        unsigned ix = (unsigned)redI[par][lane];
        unsigned gmx = redux_max_u32(__float_as_uint(v));
        unsigned ci2 = (__float_as_uint(v) == gmx) ? ix : 0x7FFFFFFFu;
        int gi = (int)redux_min_u32(ci2);
        px = sx[gi]; py = sy[gi]; pz = sz[gi];
        if (tid == 0) {
            float* ap = out + ((size_t)g * MANCH + step) * 3;
            ap[0] = px; ap[1] = py; ap[2] = pz;
        }
    }
}

// ---------------------------------------------------------------------------
// fps1: anchors [0, FPS_SPLIT) for all groups (blocks 0..63) + Wm prep
// (blocks 64..67). Stores min-dist state to gFpsDist for fps2.
// ---------------------------------------------------------------------------
__global__ void __launch_bounds__(FPS_THREADS) fps1_kernel(
    const float* __restrict__ xyzs, const float* __restrict__ Wm,
    float* __restrict__ out) {
    if (blockIdx.x >= GTOT) {
        int idx = (blockIdx.x - GTOT) * FPS_THREADS + threadIdx.x;  // 0..4095
        int r = idx & 3;
        int l = (idx >> 2) & 31;
        int fid = idx >> 7;
        int kt = fid & 3, mt = fid >> 2;
        int gid = l >> 2, tig = l & 3;
        int row = mt * 16 + gid + (r & 1) * 8;
        int ch  = kt * 16 + tig * 2 + (r >> 1) * 8;
        gWmF16[idx] = pkh2(Wm[row * GC0 + ch], Wm[row * GC0 + ch + 1]);
        return;
    }

    extern __shared__ float sm[];
    float* sx = sm;
    float* sy = sm + NPTS;
    float* sz = sm + 2 * NPTS;
    __shared__ float redV[2][32];
    __shared__ int   redI[2][32];

    int g = blockIdx.x;
    int b = g >> 4, f = g & 15;
    const float* frame = xyzs + ((size_t)(b * 32 + 2 * f)) * NPTS * 3;
    int tid = threadIdx.x, lane = tid & 31, wid = tid >> 5;

    for (int i = tid; i < NPTS; i += FPS_THREADS) {
        sx[i] = frame[3 * i + 0];
        sy[i] = frame[3 * i + 1];
        sz[i] = frame[3 * i + 2];
    }
    __syncthreads();

    FpsState st;
#pragma unroll
    for (int p = 0; p < 2; p++) {
        int i0 = tid + 2 * p * FPS_THREADS;
        st.X2[p] = pk2f(sx[i0], sx[i0 + FPS_THREADS]);
        st.Y2[p] = pk2f(sy[i0], sy[i0 + FPS_THREADS]);
        st.Z2[p] = pk2f(sz[i0], sz[i0 + FPS_THREADS]);
    }
#pragma unroll
    for (int s = 0; s < 4; s++) st.dist[s] = 1e10f;

    if (tid == 0) {
        float* ap = out + (size_t)g * MANCH * 3;
        ap[0] = sx[0]; ap[1] = sy[0]; ap[2] = sz[0];
    }
    float px = sx[0], py = sy[0], pz = sz[0];

    fps_steps(st, sx, sy, sz, redV, redI, px, py, pz,
              1, FPS_SPLIT, g, tid, lane, wid, out);

    // persist dist state (pivot = anchor FPS_SPLIT-1, read back from out)
    float* dd = gFpsDist + (size_t)g * NPTS;
#pragma unroll
    for (int s = 0; s < 4; s++) dd[tid + s * FPS_THREADS] = st.dist[s];
}

// ---------------------------------------------------------------------------
// fps2: anchors [FPS_SPLIT, 128). Resumes from gFpsDist + anchor FPS_SPLIT-1.
// ---------------------------------------------------------------------------
__global__ void __launch_bounds__(FPS_THREADS) fps2_kernel(
    const float* __restrict__ xyzs, float* __restrict__ out) {
    extern __shared__ float sm[];
    float* sx = sm;
    float* sy = sm + NPTS;
    float* sz = sm + 2 * NPTS;
    __shared__ float redV[2][32];
    __shared__ int   redI[2][32];

    int g = blockIdx.x;
    int b = g >> 4, f = g & 15;
    const float* frame = xyzs + ((size_t)(b * 32 + 2 * f)) * NPTS * 3;
    int tid = threadIdx.x, lane = tid & 31, wid = tid >> 5;

    for (int i = tid; i < NPTS; i += FPS_THREADS) {
        sx[i] = frame[3 * i + 0];
        sy[i] = frame[3 * i + 1];
        sz[i] = frame[3 * i + 2];
    }
    __syncthreads();

    FpsState st;
#pragma unroll
    for (int p = 0; p < 2; p++) {
        int i0 = tid + 2 * p * FPS_THREADS;
        st.X2[p] = pk2f(sx[i0], sx[i0 + FPS_THREADS]);
        st.Y2[p] = pk2f(sy[i0], sy[i0 + FPS_THREADS]);
        st.Z2[p] = pk2f(sz[i0], sz[i0 + FPS_THREADS]);
    }
    const float* dd = gFpsDist + (size_t)g * NPTS;
#pragma unroll
    for (int s = 0; s < 4; s++) st.dist[s] = dd[tid + s * FPS_THREADS];

    const float* lastA = out + ((size_t)g * MANCH + FPS_SPLIT - 1) * 3;
    float px = lastA[0], py = lastA[1], pz = lastA[2];

    fps_steps(st, sx, sy, sz, redV, redI, px, py, pz,
              FPS_SPLIT, MANCH, g, tid, lane, wid, out);
}

// ---------------------------------------------------------------------------
// Kernel B1: ball query for m in [mhalf*64, mhalf*64+64). Grid (3 dt, 64 g),
// block 256 = 8 warps; frame loaded once; 4-points-per-lane ballot scan.
// ---------------------------------------------------------------------------
__global__ void __launch_bounds__(256, 4) query_kernel(
    const float* __restrict__ xyzs,
    const float* __restrict__ anchors, int mhalf) {
    extern __shared__ float sm[];
    float* sx = sm;
    float* sy = sm + NPTS;
    float* sz = sm + 2 * NPTS;
    int* sidx = (int*)(sm + 3 * NPTS);   // 8 warps * 32

    int dtI = blockIdx.x, g = blockIdx.y;
    int b = g >> 4, f = g & 15;
    int tid = threadIdx.x, warp = tid >> 5, lane = tid & 31;
    int* ib = sidx + warp * KNN;

    int t = 2 * f + dtI - 1;
    t = t < 0 ? 0 : (t > 31 ? 31 : t);
    const float* frame = xyzs + ((size_t)(b * 32 + t)) * NPTS * 3;
    for (int i = tid; i < NPTS; i += 256) {
        sx[i] = frame[3 * i + 0];
        sy[i] = frame[3 * i + 1];
        sz[i] = frame[3 * i + 2];
    }
    __syncthreads();

    unsigned lt = (1u << lane) - 1u;

    for (int mi = 0; mi < 8; mi++) {
        int m = mhalf * 64 + mi * 8 + warp;
        const float* ap = anchors + ((size_t)g * MANCH + m) * 3;
        float ax = ap[0], ay = ap[1], az = ap[2];

        int count = 0;
        for (int base = 0; base < NPTS && count < KNN; base += 128) {
            int i0 = base + lane * 4;
            float4 x4 = *(const float4*)&sx[i0];
            float4 y4 = *(const float4*)&sy[i0];
            float4 z4 = *(const float4*)&sz[i0];
            bool w0 = dist2_precise(ax, ay, az, x4.x, y4.x, z4.x) < RR2;
            bool w1 = dist2_precise(ax, ay, az, x4.y, y4.y, z4.y) < RR2;
            bool w2 = dist2_precise(ax, ay, az, x4.z, y4.z, z4.z) < RR2;
            bool w3 = dist2_precise(ax, ay, az, x4.w, y4.w, z4.w) < RR2;
            unsigned m0 = __ballot_sync(0xffffffffu, w0);
            unsigned m1 = __ballot_sync(0xffffffffu, w1);
            unsigned m2 = __ballot_sync(0xffffffffu, w2);
            unsigned m3 = __ballot_sync(0xffffffffu, w3);
            int r = count + __popc(m0 & lt) + __popc(m1 & lt)
                          + __popc(m2 & lt) + __popc(m3 & lt);
            if (w0) { if (r < KNN) ib[r] = i0;     r++; }
            if (w1) { if (r < KNN) ib[r] = i0 + 1; r++; }
            if (w2) { if (r < KNN) ib[r] = i0 + 2; r++; }
            if (w3) { if (r < KNN) ib[r] = i0 + 3; r++; }
            count += __popc(m0) + __popc(m1) + __popc(m2) + __popc(m3);
        }
        __syncwarp();
        int myIdx = 0;  // no valid neighbor -> index 0 (reference semantics)
        if (count > 0) myIdx = ib[lane < count ? lane : 0];

        float* dst = gDisp + (((size_t)g * MANCH + m) * 3 + dtI) * 96;
        dst[lane]      = sx[myIdx] - ax;
        dst[32 + lane] = sy[myIdx] - ay;
        dst[64 + lane] = sz[myIdx] - az;
        __syncwarp();
    }
}

// ---------------------------------------------------------------------------
// Kernel B2: layer1 (fp32) + layer2 fp16 m16n8k16 MMA + max-over-k + sum-dt.
// Grid (8, 64) covering tiles [tile0, tile0+8); warp = one anchor.
// ---------------------------------------------------------------------------
__global__ void __launch_bounds__(256, 3) mlp_kernel(float* __restrict__ out,
                                                     int tile0) {
    extern __shared__ uint32_t smB[];   // 8 warps * 16 frags * FS words
    int tile = tile0 + blockIdx.x, g = blockIdx.y;
    int tid = threadIdx.x, warp = tid >> 5, lane = tid & 31;
    int gid = lane >> 2, tig = lane & 3;
    uint32_t* wB = smB + warp * 16 * FS;
    int m = tile * 8 + warp;

    int ntp = lane >> 3, g8 = lane & 7;

    float accM[16];
#pragma unroll
    for (int i = 0; i < 16; i++) accM[i] = 0.0f;

    for (int dtI = 0; dtI < 3; dtI++) {
        const float* src = gDisp + (((size_t)g * MANCH + m) * 3 + dtI) * 96;
        float dx = src[lane], dy = src[32 + lane], dz = src[64 + lane];
        float dtf = (float)(dtI - 1);

#pragma unroll
        for (int kt = 0; kt < 4; kt++) {
            float hv[16];
#pragma unroll
            for (int c = 0; c < 16; c++) {
                float4 w = cWd[kt * 16 + c];
                float v = fmaf(w.x, dx, fmaf(w.y, dy, fmaf(w.z, dz, w.w * dtf)));
                hv[c] = fmaxf(v, 0.0f);
            }
#pragma unroll
            for (int tg = 0; tg < 4; tg++) {
                uint2 v;
                v.x = pkh2(hv[2 * tg],     hv[2 * tg + 1]);
                v.y = pkh2(hv[2 * tg + 8], hv[2 * tg + 9]);
                *(uint2*)(wB + (kt * 4 + ntp) * FS + (g8 * 4 + tg) * 2) = v;
            }
        }
        __syncwarp();

#pragma unroll 1
        for (int mt = 0; mt < 8; mt++) {
            float d[4][4];
#pragma unroll
            for (int nt = 0; nt < 4; nt++)
#pragma unroll
                for (int r = 0; r < 4; r++) d[nt][r] = 0.0f;

#pragma unroll
            for (int kt = 0; kt < 4; kt++) {
                uint4 afr = *(const uint4*)&gWmF16[((mt * 4 + kt) * 32 + lane) * 4];
#pragma unroll
                for (int nt = 0; nt < 4; nt++) {
                    uint2 bf = *(const uint2*)(wB + (kt * 4 + nt) * FS + lane * 2);
                    mma_f16(d[nt][0], d[nt][1], d[nt][2], d[nt][3],
                            afr.x, afr.y, afr.z, afr.w, bf.x, bf.y);
                }
            }
            float mlo = fmaxf(d[0][0], d[0][1]);
            float mhi = fmaxf(d[0][2], d[0][3]);
#pragma unroll
            for (int nt = 1; nt < 4; nt++) {
                mlo = fmaxf(mlo, fmaxf(d[nt][0], d[nt][1]));
                mhi = fmaxf(mhi, fmaxf(d[nt][2], d[nt][3]));
            }
            mlo = fmaxf(mlo, __shfl_xor_sync(0xffffffffu, mlo, 1));
            mlo = fmaxf(mlo, __shfl_xor_sync(0xffffffffu, mlo, 2));
            mhi = fmaxf(mhi, __shfl_xor_sync(0xffffffffu, mhi, 1));
            mhi = fmaxf(mhi, __shfl_xor_sync(0xffffffffu, mhi, 2));
            accM[2 * mt]     += fmaxf(mlo, 0.0f);
            accM[2 * mt + 1] += fmaxf(mhi, 0.0f);
        }
        __syncwarp();
    }

    float* feat = out + (size_t)GTOT * MANCH * 3;
    if (tig == 0) {
#pragma unroll
        for (int mt = 0; mt < 8; mt++) {
            int o_lo = mt * 16 + gid;
            feat[((size_t)g * GC1 + o_lo) * MANCH + m]     = accM[2 * mt];
            feat[((size_t)g * GC1 + o_lo + 8) * MANCH + m] = accM[2 * mt + 1];
        }
    }
}

extern "C" void kernel_launch(void* const* d_in, const int* in_sizes, int n_in,
                              void* d_out, int out_size) {
    const float* xyzs = (const float*)d_in[0];
    const float* Wd   = (const float*)d_in[1];
    const float* Wm   = (const float*)d_in[2];
    float* out = (float*)d_out;

    size_t smF = (size_t)3 * NPTS * sizeof(float);                    // 48K
    size_t smQ = smF + (size_t)8 * KNN * sizeof(int);                 // 49K
    size_t smM = (size_t)8 * 16 * FS * sizeof(uint32_t);              // 33K

    cudaFuncSetAttribute(fps1_kernel,  cudaFuncAttributeMaxDynamicSharedMemorySize, (int)smF);
    cudaFuncSetAttribute(fps2_kernel,  cudaFuncAttributeMaxDynamicSharedMemorySize, (int)smF);
    cudaFuncSetAttribute(query_kernel, cudaFuncAttributeMaxDynamicSharedMemorySize, (int)smQ);
    cudaFuncSetAttribute(mlp_kernel,   cudaFuncAttributeMaxDynamicSharedMemorySize, (int)smM);

    // side stream + fork/join events (host objects; created per call)
    cudaStream_t s2;
    cudaStreamCreate(&s2);
    cudaEvent_t eA, eB;
    cudaEventCreateWithFlags(&eA, cudaEventDisableTiming);
    cudaEventCreateWithFlags(&eB, cudaEventDisableTiming);

    cudaMemcpyToSymbolAsync(cWd, Wd, GC0 * 4 * sizeof(float), 0,
                            cudaMemcpyDeviceToDevice);

    // s0: fps1 (anchors 0..63 + prep)
    fps1_kernel<<<GTOT + 4, FPS_THREADS, smF>>>(xyzs, Wm, out);
    cudaEventRecord(eA, 0);

    // s2 (forked): fps2 -> query for m 64..127
    cudaStreamWaitEvent(s2, eA, 0);
    fps2_kernel<<<GTOT, FPS_THREADS, smF, s2>>>(xyzs, out);
    query_kernel<<<dim3(3, GTOT), 256, smQ, s2>>>(xyzs, out, 1);
    cudaEventRecord(eB, s2);

    // s0: query + mlp for m 0..63 (runs concurrently with s2)
    query_kernel<<<dim3(3, GTOT), 256, smQ>>>(xyzs, out, 0);
    mlp_kernel<<<dim3(8, GTOT), 256, smM>>>(out, 0);

    // join, then mlp for m 64..127
    cudaStreamWaitEvent(0, eB, 0);
    mlp_kernel<<<dim3(8, GTOT), 256, smM>>>(out, 8);

    cudaEventDestroy(eA);
    cudaEventDestroy(eB);
    cudaStreamDestroy(s2);
}

// round 16
// speedup vs baseline: 1.0383x; 1.0383x over previous
#include <cuda_runtime.h>
#include <cuda_fp16.h>
#include <cstdint>
#include <cstddef>

#define NPTS   4096
#define MANCH  128
#define GC0    64
#define GC1    128
#define KNN    32
#define RR2    0.0225f
#define GTOT   64
#define FPS_THREADS 1024
#define FS     66    // B-fragment stride in words (64 + 2 pad)

// Layer-1 weights (1KB — const-cache resident, warp-uniform reads)
__constant__ float4 cWd[GC0];
// Layer-2 weights as fp16x2 in m16n8k16 A-fragment layout (16KB, L1-resident)
__device__ uint32_t gWmF16[8 * 4 * 128];
// Ball-query output: [g][m][dt][c(3)][k(32)] fp32 displacements (9.4MB)
__device__ float gDisp[(size_t)GTOT * MANCH * 3 * 96];

// Exact (non-FMA-contracted) squared distance: discrete decisions
// (radius threshold) match the JAX reference bit-for-bit.
__device__ __forceinline__ float dist2_precise(float ax, float ay, float az,
                                               float bx, float by, float bz) {
    float dx = __fsub_rn(ax, bx);
    float dy = __fsub_rn(ay, by);
    float dz = __fsub_rn(az, bz);
    return __fadd_rn(__fadd_rn(__fmul_rn(dx, dx), __fmul_rn(dy, dy)),
                     __fmul_rn(dz, dz));
}

// ---- packed f32x2 helpers (per-lane rounding identical to scalar ops) ----
typedef unsigned long long u64t;
__device__ __forceinline__ u64t pk2f(float lo, float hi) {
    u64t r; asm("mov.b64 %0, {%1, %2};" : "=l"(r) : "f"(lo), "f"(hi)); return r;
}
__device__ __forceinline__ void upk2f(float& lo, float& hi, u64t v) {
    asm("mov.b64 {%0, %1}, %2;" : "=f"(lo), "=f"(hi) : "l"(v));
}
__device__ __forceinline__ u64t sub2(u64t a, u64t b) {
    u64t d; asm("sub.rn.f32x2 %0, %1, %2;" : "=l"(d) : "l"(a), "l"(b)); return d;
}
__device__ __forceinline__ u64t mul2(u64t a, u64t b) {
    u64t d; asm("mul.rn.f32x2 %0, %1, %2;" : "=l"(d) : "l"(a), "l"(b)); return d;
}
__device__ __forceinline__ u64t add2(u64t a, u64t b) {
    u64t d; asm("add.rn.f32x2 %0, %1, %2;" : "=l"(d) : "l"(a), "l"(b)); return d;
}

__device__ __forceinline__ unsigned redux_max_u32(unsigned v) {
    unsigned r;
    asm("redux.sync.max.u32 %0, %1, 0xffffffff;" : "=r"(r) : "r"(v));
    return r;
}
__device__ __forceinline__ unsigned redux_min_u32(unsigned v) {
    unsigned r;
    asm("redux.sync.min.u32 %0, %1, 0xffffffff;" : "=r"(r) : "r"(v));
    return r;
}

// pack two fp32 -> fp16x2 (lo in low half)
__device__ __forceinline__ uint32_t pkh2(float lo, float hi) {
    uint32_t r;
    asm("cvt.rn.f16x2.f32 %0, %1, %2;" : "=r"(r) : "f"(hi), "f"(lo));
    return r;
}

__device__ __forceinline__ void mma_f16(float& d0, float& d1, float& d2, float& d3,
                                        uint32_t a0, uint32_t a1, uint32_t a2, uint32_t a3,
                                        uint32_t b0, uint32_t b1) {
    asm volatile(
        "mma.sync.aligned.m16n8k16.row.col.f32.f16.f16.f32 "
        "{%0,%1,%2,%3}, {%4,%5,%6,%7}, {%8,%9}, {%0,%1,%2,%3};"
        : "+f"(d0), "+f"(d1), "+f"(d2), "+f"(d3)
        : "r"(a0), "r"(a1), "r"(a2), "r"(a3), "r"(b0), "r"(b1));
}

// ---------------------------------------------------------------------------
// Kernel A: FPS (blocks 0..63) + Wm fragment prep (blocks 64..67).
// Packed f32x2 distance arithmetic (bit-exact per lane); deferred argmax
// with exact first-occurrence tie-break (matches jnp.argmax).
// ---------------------------------------------------------------------------
__global__ void __launch_bounds__(FPS_THREADS) fps_kernel(
    const float* __restrict__ xyzs, const float* __restrict__ Wm,
    float* __restrict__ out) {
    if (blockIdx.x >= GTOT) {
        int idx = (blockIdx.x - GTOT) * FPS_THREADS + threadIdx.x;  // 0..4095
        int r = idx & 3;
        int l = (idx >> 2) & 31;
        int fid = idx >> 7;
        int kt = fid & 3, mt = fid >> 2;
        int gid = l >> 2, tig = l & 3;
        int row = mt * 16 + gid + (r & 1) * 8;
        int ch  = kt * 16 + tig * 2 + (r >> 1) * 8;
        gWmF16[idx] = pkh2(Wm[row * GC0 + ch], Wm[row * GC0 + ch + 1]);
        return;
    }

    extern __shared__ float sm[];
    float* sx = sm;
    float* sy = sm + NPTS;
    float* sz = sm + 2 * NPTS;
    __shared__ float redV[2][32];
    __shared__ int   redI[2][32];

    int g = blockIdx.x;
    int b = g >> 4, f = g & 15;
    const float* frame = xyzs + ((size_t)(b * 32 + 2 * f)) * NPTS * 3;
    int tid = threadIdx.x, lane = tid & 31, wid = tid >> 5;

    for (int i = tid; i < NPTS; i += FPS_THREADS) {
        sx[i] = frame[3 * i + 0];
        sy[i] = frame[3 * i + 1];
        sz[i] = frame[3 * i + 2];
    }
    __syncthreads();

    u64t X2[2], Y2[2], Z2[2];
    float dist[4];
#pragma unroll
    for (int p = 0; p < 2; p++) {
        int i0 = tid + 2 * p * FPS_THREADS;
        X2[p] = pk2f(sx[i0], sx[i0 + FPS_THREADS]);
        Y2[p] = pk2f(sy[i0], sy[i0 + FPS_THREADS]);
        Z2[p] = pk2f(sz[i0], sz[i0 + FPS_THREADS]);
    }
#pragma unroll
    for (int s = 0; s < 4; s++) dist[s] = 1e10f;

    if (tid == 0) {
        float* ap = out + (size_t)g * MANCH * 3;
        ap[0] = sx[0]; ap[1] = sy[0]; ap[2] = sz[0];
    }
    float px = sx[0], py = sy[0], pz = sz[0];

    for (int step = 1; step < MANCH; step++) {
        int par = step & 1;
        u64t pxx = pk2f(px, px), pyy = pk2f(py, py), pzz = pk2f(pz, pz);
        float nd[4];
#pragma unroll
        for (int p = 0; p < 2; p++) {
            u64t dx = sub2(X2[p], pxx);
            u64t dy = sub2(Y2[p], pyy);
            u64t dz = sub2(Z2[p], pzz);
            u64t d2 = add2(add2(mul2(dx, dx), mul2(dy, dy)), mul2(dz, dz));
            upk2f(nd[2 * p], nd[2 * p + 1], d2);
        }
        float bv = -1.0f;
#pragma unroll
        for (int s = 0; s < 4; s++) {
            dist[s] = fminf(dist[s], nd[s]);
            bv = fmaxf(bv, dist[s]);
        }
        unsigned wm = redux_max_u32(__float_as_uint(bv));
        unsigned ci = 0x7FFFFFFFu;
        if (__float_as_uint(dist[3]) == wm) ci = (unsigned)(tid + 3 * FPS_THREADS);
        if (__float_as_uint(dist[2]) == wm) ci = (unsigned)(tid + 2 * FPS_THREADS);
        if (__float_as_uint(dist[1]) == wm) ci = (unsigned)(tid + FPS_THREADS);
        if (__float_as_uint(dist[0]) == wm) ci = (unsigned)tid;
        unsigned wi = redux_min_u32(ci);
        if (lane == 0) { redV[par][wid] = __uint_as_float(wm); redI[par][wid] = (int)wi; }
        __syncthreads();
        float    v  = redV[par][lane];
        unsigned ix = (unsigned)redI[par][lane];
        unsigned gmx = redux_max_u32(__float_as_uint(v));
        unsigned ci2 = (__float_as_uint(v) == gmx) ? ix : 0x7FFFFFFFu;
        int gi = (int)redux_min_u32(ci2);
        px = sx[gi]; py = sy[gi]; pz = sz[gi];
        if (tid == 0) {
            float* ap = out + ((size_t)g * MANCH + step) * 3;
            ap[0] = px; ap[1] = py; ap[2] = pz;
        }
    }
}

// ---------------------------------------------------------------------------
// Kernel B1: ball query. Grid (3 dt, 64 g, 2 half), block 256 = 8 warps.
// TWO anchors per warp interleaved in one scan (shared point loads, 2 ILP
// chains); exact first-KNN-ascending semantics per anchor.
// ---------------------------------------------------------------------------
__global__ void __launch_bounds__(256, 4) query_kernel(
    const float* __restrict__ xyzs,
    const float* __restrict__ anchors) {
    extern __shared__ float sm[];
    float* sx = sm;
    float* sy = sm + NPTS;
    float* sz = sm + 2 * NPTS;
    int* sidx = (int*)(sm + 3 * NPTS);   // 8 warps * 64

    int dtI = blockIdx.x, g = blockIdx.y, half = blockIdx.z;
    int b = g >> 4, f = g & 15;
    int tid = threadIdx.x, warp = tid >> 5, lane = tid & 31;
    int* ibA = sidx + warp * 2 * KNN;
    int* ibB = ibA + KNN;

    int t = 2 * f + dtI - 1;
    t = t < 0 ? 0 : (t > 31 ? 31 : t);
    const float* frame = xyzs + ((size_t)(b * 32 + t)) * NPTS * 3;
    for (int i = tid; i < NPTS; i += 256) {
        sx[i] = frame[3 * i + 0];
        sy[i] = frame[3 * i + 1];
        sz[i] = frame[3 * i + 2];
    }
    __syncthreads();

    unsigned lt = (1u << lane) - 1u;

    for (int pr = 0; pr < 4; pr++) {
        int mA = half * 64 + pr * 8 + warp;
        int mB = mA + 32;
        const float* apA = anchors + ((size_t)g * MANCH + mA) * 3;
        const float* apB = anchors + ((size_t)g * MANCH + mB) * 3;
        float axA = apA[0], ayA = apA[1], azA = apA[2];
        float axB = apB[0], ayB = apB[1], azB = apB[2];

        int cA = 0, cB = 0;
        for (int base = 0; base < NPTS && (cA < KNN || cB < KNN); base += 128) {
            int i0 = base + lane * 4;
            float4 x4 = *(const float4*)&sx[i0];
            float4 y4 = *(const float4*)&sy[i0];
            float4 z4 = *(const float4*)&sz[i0];
            if (cA < KNN) {
                bool w0 = dist2_precise(axA, ayA, azA, x4.x, y4.x, z4.x) < RR2;
                bool w1 = dist2_precise(axA, ayA, azA, x4.y, y4.y, z4.y) < RR2;
                bool w2 = dist2_precise(axA, ayA, azA, x4.z, y4.z, z4.z) < RR2;
                bool w3 = dist2_precise(axA, ayA, azA, x4.w, y4.w, z4.w) < RR2;
                unsigned m0 = __ballot_sync(0xffffffffu, w0);
                unsigned m1 = __ballot_sync(0xffffffffu, w1);
                unsigned m2 = __ballot_sync(0xffffffffu, w2);
                unsigned m3 = __ballot_sync(0xffffffffu, w3);
                int r = cA + __popc(m0 & lt) + __popc(m1 & lt)
                           + __popc(m2 & lt) + __popc(m3 & lt);
                if (w0) { if (r < KNN) ibA[r] = i0;     r++; }
                if (w1) { if (r < KNN) ibA[r] = i0 + 1; r++; }
                if (w2) { if (r < KNN) ibA[r] = i0 + 2; r++; }
                if (w3) { if (r < KNN) ibA[r] = i0 + 3; r++; }
                cA += __popc(m0) + __popc(m1) + __popc(m2) + __popc(m3);
            }
            if (cB < KNN) {
                bool w0 = dist2_precise(axB, ayB, azB, x4.x, y4.x, z4.x) < RR2;
                bool w1 = dist2_precise(axB, ayB, azB, x4.y, y4.y, z4.y) < RR2;
                bool w2 = dist2_precise(axB, ayB, azB, x4.z, y4.z, z4.z) < RR2;
                bool w3 = dist2_precise(axB, ayB, azB, x4.w, y4.w, z4.w) < RR2;
                unsigned m0 = __ballot_sync(0xffffffffu, w0);
                unsigned m1 = __ballot_sync(0xffffffffu, w1);
                unsigned m2 = __ballot_sync(0xffffffffu, w2);
                unsigned m3 = __ballot_sync(0xffffffffu, w3);
                int r = cB + __popc(m0 & lt) + __popc(m1 & lt)
                           + __popc(m2 & lt) + __popc(m3 & lt);
                if (w0) { if (r < KNN) ibB[r] = i0;     r++; }
                if (w1) { if (r < KNN) ibB[r] = i0 + 1; r++; }
                if (w2) { if (r < KNN) ibB[r] = i0 + 2; r++; }
                if (w3) { if (r < KNN) ibB[r] = i0 + 3; r++; }
                cB += __popc(m0) + __popc(m1) + __popc(m2) + __popc(m3);
            }
        }
        __syncwarp();
        int idxA = 0, idxB = 0;   // no valid neighbor -> index 0
        if (cA > 0) idxA = ibA[lane < cA ? lane : 0];
        if (cB > 0) idxB = ibB[lane < cB ? lane : 0];

        float* dA = gDisp + (((size_t)g * MANCH + mA) * 3 + dtI) * 96;
        dA[lane]      = sx[idxA] - axA;
        dA[32 + lane] = sy[idxA] - ayA;
        dA[64 + lane] = sz[idxA] - azA;
        float* dB = gDisp + (((size_t)g * MANCH + mB) * 3 + dtI) * 96;
        dB[lane]      = sx[idxB] - axB;
        dB[32 + lane] = sy[idxB] - ayB;
        dB[64 + lane] = sz[idxB] - azB;
        __syncwarp();
    }
}

// ---------------------------------------------------------------------------
// Kernel B2: layer1 (fp32) + layer2 fp16 m16n8k16 MMA + max-over-k + sum-dt.
// Grid (16,64), block 256 = 8 warps, warp = one anchor (3 dts in sequence).
// ---------------------------------------------------------------------------
__global__ void __launch_bounds__(256, 3) mlp_kernel(float* __restrict__ out) {
    extern __shared__ uint32_t smB[];   // 8 warps * 16 frags * FS words
    int tile = blockIdx.x, g = blockIdx.y;
    int tid = threadIdx.x, warp = tid >> 5, lane = tid & 31;
    int gid = lane >> 2, tig = lane & 3;
    uint32_t* wB = smB + warp * 16 * FS;
    int m = tile * 8 + warp;

    int ntp = lane >> 3, g8 = lane & 7;

    float accM[16];
#pragma unroll
    for (int i = 0; i < 16; i++) accM[i] = 0.0f;

    for (int dtI = 0; dtI < 3; dtI++) {
        const float* src = gDisp + (((size_t)g * MANCH + m) * 3 + dtI) * 96;
        float dx = src[lane], dy = src[32 + lane], dz = src[64 + lane];
        float dtf = (float)(dtI - 1);

#pragma unroll
        for (int kt = 0; kt < 4; kt++) {
            float hv[16];
#pragma unroll
            for (int c = 0; c < 16; c++) {
                float4 w = cWd[kt * 16 + c];
                float v = fmaf(w.x, dx, fmaf(w.y, dy, fmaf(w.z, dz, w.w * dtf)));
                hv[c] = fmaxf(v, 0.0f);
            }
#pragma unroll
            for (int tg = 0; tg < 4; tg++) {
                uint2 v;
                v.x = pkh2(hv[2 * tg],     hv[2 * tg + 1]);
                v.y = pkh2(hv[2 * tg + 8], hv[2 * tg + 9]);
                *(uint2*)(wB + (kt * 4 + ntp) * FS + (g8 * 4 + tg) * 2) = v;
            }
        }
        __syncwarp();

#pragma unroll 1
        for (int mt = 0; mt < 8; mt++) {
            float d[4][4];
#pragma unroll
            for (int nt = 0; nt < 4; nt++)
#pragma unroll
                for (int r = 0; r < 4; r++) d[nt][r] = 0.0f;

#pragma unroll
            for (int kt = 0; kt < 4; kt++) {
                uint4 afr = *(const uint4*)&gWmF16[((mt * 4 + kt) * 32 + lane) * 4];
#pragma unroll
                for (int nt = 0; nt < 4; nt++) {
                    uint2 bf = *(const uint2*)(wB + (kt * 4 + nt) * FS + lane * 2);
                    mma_f16(d[nt][0], d[nt][1], d[nt][2], d[nt][3],
                            afr.x, afr.y, afr.z, afr.w, bf.x, bf.y);
                }
            }
            float mlo = fmaxf(d[0][0], d[0][1]);
            float mhi = fmaxf(d[0][2], d[0][3]);
#pragma unroll
            for (int nt = 1; nt < 4; nt++) {
                mlo = fmaxf(mlo, fmaxf(d[nt][0], d[nt][1]));
                mhi = fmaxf(mhi, fmaxf(d[nt][2], d[nt][3]));
            }
            mlo = fmaxf(mlo, __shfl_xor_sync(0xffffffffu, mlo, 1));
            mlo = fmaxf(mlo, __shfl_xor_sync(0xffffffffu, mlo, 2));
            mhi = fmaxf(mhi, __shfl_xor_sync(0xffffffffu, mhi, 1));
            mhi = fmaxf(mhi, __shfl_xor_sync(0xffffffffu, mhi, 2));
            accM[2 * mt]     += fmaxf(mlo, 0.0f);
            accM[2 * mt + 1] += fmaxf(mhi, 0.0f);
        }
        __syncwarp();
    }

    float* feat = out + (size_t)GTOT * MANCH * 3;
    if (tig == 0) {
#pragma unroll
        for (int mt = 0; mt < 8; mt++) {
            int o_lo = mt * 16 + gid;
            feat[((size_t)g * GC1 + o_lo) * MANCH + m]     = accM[2 * mt];
            feat[((size_t)g * GC1 + o_lo + 8) * MANCH + m] = accM[2 * mt + 1];
        }
    }
}

extern "C" void kernel_launch(void* const* d_in, const int* in_sizes, int n_in,
                              void* d_out, int out_size) {
    const float* xyzs = (const float*)d_in[0];
    const float* Wd   = (const float*)d_in[1];
    const float* Wm   = (const float*)d_in[2];
    float* out = (float*)d_out;

    cudaMemcpyToSymbolAsync(cWd, Wd, GC0 * 4 * sizeof(float), 0,
                            cudaMemcpyDeviceToDevice);

    size_t smF = (size_t)3 * NPTS * sizeof(float);                    // 48K
    size_t smQ = smF + (size_t)8 * 2 * KNN * sizeof(int);             // 50K
    size_t smM = (size_t)8 * 16 * FS * sizeof(uint32_t);              // 33K

    cudaFuncSetAttribute(fps_kernel,   cudaFuncAttributeMaxDynamicSharedMemorySize, (int)smF);
    cudaFuncSetAttribute(query_kernel, cudaFuncAttributeMaxDynamicSharedMemorySize, (int)smQ);
    cudaFuncSetAttribute(mlp_kernel,   cudaFuncAttributeMaxDynamicSharedMemorySize, (int)smM);

    fps_kernel<<<GTOT + 4, FPS_THREADS, smF>>>(xyzs, Wm, out);   // fps + prep
    query_kernel<<<dim3(3, GTOT, 2), 256, smQ>>>(xyzs, out);
    mlp_kernel<<<dim3(16, GTOT), 256, smM>>>(out);
}